// round 1
// baseline (speedup 1.0000x reference)
#include <cuda_runtime.h>

typedef unsigned long long ULL;

// ---------------- packed f32x2 helpers (sm_103a FFMA2 path) ----------------
__device__ __forceinline__ ULL pk2(float lo, float hi) {
    ULL r; asm("mov.b64 %0, {%1,%2};" : "=l"(r) : "f"(lo), "f"(hi)); return r;
}
__device__ __forceinline__ void upk2(ULL v, float& lo, float& hi) {
    asm("mov.b64 {%0,%1}, %2;" : "=f"(lo), "=f"(hi) : "l"(v));
}
__device__ __forceinline__ ULL fma2(ULL a, ULL b, ULL c) {
    ULL d; asm("fma.rn.f32x2 %0, %1, %2, %3;" : "=l"(d) : "l"(a), "l"(b), "l"(c)); return d;
}
__device__ __forceinline__ ULL add2(ULL a, ULL b) {
    ULL d; asm("add.rn.f32x2 %0, %1, %2;" : "=l"(d) : "l"(a), "l"(b)); return d;
}

// ---------------- problem constants ----------------
constexpr int K  = 32;    // experts
constexpr int DI = 10;    // input size
constexpr int DH = 20;    // hidden size
constexpr int B  = 262144;
constexpr int THREADS = 256;
constexpr int PAIRS_PER_CTA = THREADS;           // each thread handles 2 batch rows
constexpr int GRID = B / (2 * PAIRS_PER_CTA);    // 512 CTAs

// shared layout (floats), everything duplicated into (v,v) pairs for LDS.64
constexpr int SM_W1 = K * DH * DI * 2;  // 12800  (w,w) per W1 element
constexpr int SM_BW = K * DH * 4;       // 2560   (b1,b1,w2,w2) per (k,h)
constexpr int SM_P  = K * DI * 2;       // 640    (-p,-p)
constexpr int SM_B2 = K * 2;            // 64     (b2,b2)
constexpr int OFF_W1 = 0;
constexpr int OFF_BW = OFF_W1 + SM_W1;
constexpr int OFF_P  = OFF_BW + SM_BW;
constexpr int OFF_B2 = OFF_P  + SM_P;
constexpr int SM_TOTAL_FLOATS = OFF_B2 + SM_B2;  // 16064 floats = 64256 B

__global__ void __launch_bounds__(THREADS, 2)
piecewise_mlp_kernel(const float* __restrict__ in,
                     const float* __restrict__ W1,
                     const float* __restrict__ b1,
                     const float* __restrict__ W2,
                     const float* __restrict__ b2,
                     const float* __restrict__ proto,
                     float* __restrict__ out)
{
    extern __shared__ float sm[];

    // ---- stage weights into shared, duplicated as (v,v) pairs ----
    for (int idx = threadIdx.x; idx < K * DH * DI; idx += THREADS) {
        float w = W1[idx];
        sm[OFF_W1 + 2 * idx + 0] = w;
        sm[OFF_W1 + 2 * idx + 1] = w;
    }
    for (int idx = threadIdx.x; idx < K * DH; idx += THREADS) {
        float bb = b1[idx];
        float ww = W2[idx];            // W2 is [K,1,DH] -> flat [K*DH]
        sm[OFF_BW + 4 * idx + 0] = bb;
        sm[OFF_BW + 4 * idx + 1] = bb;
        sm[OFF_BW + 4 * idx + 2] = ww;
        sm[OFF_BW + 4 * idx + 3] = ww;
    }
    for (int idx = threadIdx.x; idx < K * DI; idx += THREADS) {
        float p = -proto[idx];         // pre-negate: diff = x + (-p)
        sm[OFF_P + 2 * idx + 0] = p;
        sm[OFF_P + 2 * idx + 1] = p;
    }
    for (int idx = threadIdx.x; idx < K; idx += THREADS) {
        float v = b2[idx];
        sm[OFF_B2 + 2 * idx + 0] = v;
        sm[OFF_B2 + 2 * idx + 1] = v;
    }
    __syncthreads();

    // ---- load 2 batch rows per thread (80 B contiguous, 16B-aligned) ----
    const int gt = blockIdx.x * THREADS + threadIdx.x;      // pair index
    const float4* q = (const float4*)(in + (size_t)gt * 2 * DI);
    float a[2 * DI];
    {
        float4 v0 = q[0], v1 = q[1], v2 = q[2], v3 = q[3], v4 = q[4];
        a[0]=v0.x; a[1]=v0.y; a[2]=v0.z; a[3]=v0.w;
        a[4]=v1.x; a[5]=v1.y; a[6]=v1.z; a[7]=v1.w;
        a[8]=v2.x; a[9]=v2.y; a[10]=v2.z; a[11]=v2.w;
        a[12]=v3.x; a[13]=v3.y; a[14]=v3.z; a[15]=v3.w;
        a[16]=v4.x; a[17]=v4.y; a[18]=v4.z; a[19]=v4.w;
    }
    ULL x2[DI];
    #pragma unroll
    for (int i = 0; i < DI; i++) x2[i] = pk2(a[i], a[DI + i]);

    const ULL* sW1p = (const ULL*)(sm + OFF_W1);   // pair units
    const ULL* sBWp = (const ULL*)(sm + OFF_BW);   // 2 pairs per (k,h): (b1,b1),(w2,w2)
    const ULL* sPp  = (const ULL*)(sm + OFF_P);
    const ULL* sB2p = (const ULL*)(sm + OFF_B2);

    ULL num2 = 0ull;   // (0.0f, 0.0f)
    ULL den2 = 0ull;

    #pragma unroll 1
    for (int k = 0; k < K; k++) {
        // ---- distance to prototype k (packed over both batch rows) ----
        ULL d2 = 0ull;
        const ULL* pp = sPp + k * DI;
        #pragma unroll
        for (int i = 0; i < DI; i += 2) {
            ulonglong2 pn = *(const ulonglong2*)(pp + i);
            ULL df0 = add2(x2[i],     pn.x);
            ULL df1 = add2(x2[i + 1], pn.y);
            d2 = fma2(df0, df0, d2);
            d2 = fma2(df1, df1, d2);
        }
        float dl, dh; upk2(d2, dl, dh);
        float el = __expf(-sqrtf(dl));
        float eh = __expf(-sqrtf(dh));
        ULL e2 = pk2(el, eh);
        den2 = add2(den2, e2);

        // ---- expert k MLP (packed): pred = b2 + sum_h relu(b1 + W1.x) * w2 ----
        ULL pred2 = sB2p[k];
        const ULL* wk = sW1p + k * DH * DI;
        const ULL* bk = sBWp + k * DH * 2;
        #pragma unroll
        for (int h = 0; h < DH; h++) {
            ulonglong2 bw = *(const ulonglong2*)(bk + 2 * h); // (b1,b1),(w2,w2)
            ULL acc2 = bw.x;
            const ULL* wh = wk + h * DI;
            #pragma unroll
            for (int i = 0; i < DI; i += 2) {
                ulonglong2 wv = *(const ulonglong2*)(wh + i);
                acc2 = fma2(x2[i],     wv.x, acc2);
                acc2 = fma2(x2[i + 1], wv.y, acc2);
            }
            float hl, hh; upk2(acc2, hl, hh);
            hl = fmaxf(hl, 0.0f);
            hh = fmaxf(hh, 0.0f);
            pred2 = fma2(pk2(hl, hh), bw.y, pred2);
        }
        num2 = fma2(pred2, e2, num2);
    }

    float nl, nh, del, deh;
    upk2(num2, nl, nh);
    upk2(den2, del, deh);
    float2 o;
    o.x = nl / del;
    o.y = nh / deh;
    ((float2*)out)[gt] = o;
}

extern "C" void kernel_launch(void* const* d_in, const int* in_sizes, int n_in,
                              void* d_out, int out_size)
{
    const float* in    = (const float*)d_in[0];
    const float* W1    = (const float*)d_in[1];
    const float* b1    = (const float*)d_in[2];
    const float* W2    = (const float*)d_in[3];
    const float* b2    = (const float*)d_in[4];
    const float* proto = (const float*)d_in[5];
    float* out = (float*)d_out;

    // 64.3 KB dynamic smem > 48 KB default: opt in (idempotent, not a stream op)
    cudaFuncSetAttribute(piecewise_mlp_kernel,
                         cudaFuncAttributeMaxDynamicSharedMemorySize,
                         SM_TOTAL_FLOATS * (int)sizeof(float));

    piecewise_mlp_kernel<<<GRID, THREADS, SM_TOTAL_FLOATS * sizeof(float)>>>(
        in, W1, b1, W2, b2, proto, out);
}

// round 2
// speedup vs baseline: 1.3435x; 1.3435x over previous
#include <cuda_runtime.h>

typedef unsigned long long ULL;

// ---------------- packed f32x2 helpers (sm_103a FFMA2 path) ----------------
__device__ __forceinline__ ULL pk2(float lo, float hi) {
    ULL r; asm("mov.b64 %0, {%1,%2};" : "=l"(r) : "f"(lo), "f"(hi)); return r;
}
__device__ __forceinline__ void upk2(ULL v, float& lo, float& hi) {
    asm("mov.b64 {%0,%1}, %2;" : "=f"(lo), "=f"(hi) : "l"(v));
}
__device__ __forceinline__ ULL fma2(ULL a, ULL b, ULL c) {
    ULL d; asm("fma.rn.f32x2 %0, %1, %2, %3;" : "=l"(d) : "l"(a), "l"(b), "l"(c)); return d;
}
__device__ __forceinline__ ULL add2(ULL a, ULL b) {
    ULL d; asm("add.rn.f32x2 %0, %1, %2;" : "=l"(d) : "l"(a), "l"(b)); return d;
}

// ---------------- problem constants ----------------
constexpr int K   = 32;   // experts
constexpr int DI  = 10;   // input size
constexpr int DH  = 20;   // hidden size
constexpr int NHP = DH / 2;  // hidden pairs = 10
constexpr int B   = 262144;
constexpr int THREADS = 128;
constexpr int R   = 4;    // batch rows per thread
constexpr int GRID = B / (R * THREADS);   // 512

// shared layout in ULL (8B) units — all natural (h,h+1) pairs, NO duplication
constexpr int U_W1 = 0;                    // [k][hp][i] : K*NHP*DI = 3200 ULL
constexpr int U_BW = U_W1 + K * NHP * DI;  // [k][hp][{b1pair,w2pair}] : K*NHP*2 = 640 ULL
constexpr int U_P  = U_BW + K * NHP * 2;   // [k][i] dup (-p,-p) : K*DI = 320 ULL
constexpr int U_END = U_P + K * DI;        // 4160 ULL
constexpr int F_B2 = U_END * 2;            // float index 8320
constexpr int SM_FLOATS = F_B2 + K;        // 8352 floats = 33408 B

__global__ void __launch_bounds__(THREADS)
piecewise_mlp_kernel(const float* __restrict__ in,
                     const float* __restrict__ W1,
                     const float* __restrict__ b1,
                     const float* __restrict__ W2,
                     const float* __restrict__ b2,
                     const float* __restrict__ proto,
                     float* __restrict__ out)
{
    extern __shared__ float sm[];
    ULL* smU = (ULL*)sm;

    // ---- stage weights: natural (h,h+1) pairs ----
    for (int idx = threadIdx.x; idx < K * NHP * DI; idx += THREADS) {
        int k = idx / (NHP * DI), rem = idx % (NHP * DI);
        int hp = rem / DI, i = rem % DI;
        float lo = W1[(k * DH + 2 * hp) * DI + i];
        float hi = W1[(k * DH + 2 * hp + 1) * DI + i];
        smU[U_W1 + idx] = pk2(lo, hi);
    }
    for (int idx = threadIdx.x; idx < K * NHP * 2; idx += THREADS) {
        int k = idx / (NHP * 2), rem = idx % (NHP * 2);
        int hp = rem / 2, w = rem % 2;
        float lo, hi;
        if (w == 0) { lo = b1[k * DH + 2 * hp]; hi = b1[k * DH + 2 * hp + 1]; }
        else        { lo = W2[k * DH + 2 * hp]; hi = W2[k * DH + 2 * hp + 1]; }
        smU[U_BW + idx] = pk2(lo, hi);
    }
    for (int idx = threadIdx.x; idx < K * DI; idx += THREADS) {
        float p = -proto[idx];                 // pre-negate: diff = x + (-p)
        smU[U_P + idx] = pk2(p, p);
    }
    for (int idx = threadIdx.x; idx < K; idx += THREADS)
        sm[F_B2 + idx] = b2[idx];
    __syncthreads();

    // ---- load R=4 batch rows (160B contiguous), build dup packs (x,x) ----
    const int gt = blockIdx.x * THREADS + threadIdx.x;
    const float4* q = (const float4*)(in + (size_t)gt * R * DI);
    ULL x2[R][DI];
    #pragma unroll
    for (int v = 0; v < R * DI / 4; v++) {     // 10 float4 loads
        float4 f = q[v];
        int b0 = v * 4;
        x2[(b0 + 0) / DI][(b0 + 0) % DI] = pk2(f.x, f.x);
        x2[(b0 + 1) / DI][(b0 + 1) % DI] = pk2(f.y, f.y);
        x2[(b0 + 2) / DI][(b0 + 2) % DI] = pk2(f.z, f.z);
        x2[(b0 + 3) / DI][(b0 + 3) % DI] = pk2(f.w, f.w);
    }

    float num[R], den[R];
    #pragma unroll
    for (int r = 0; r < R; r++) { num[r] = 0.0f; den[r] = 0.0f; }

    const ULL* w1p = smU + U_W1;
    const ULL* bwp = smU + U_BW;
    const ULL* ppp = smU + U_P;

    #pragma unroll 1
    for (int k = 0; k < K; k++) {
        // ---- gating: dist + exp (dup lanes compute same value; lo half used) ----
        const ulonglong2* pk4 = (const ulonglong2*)(ppp + k * DI);
        ulonglong2 p0 = pk4[0], p1 = pk4[1], p2 = pk4[2], p3 = pk4[3], p4 = pk4[4];
        float ev[R];
        #pragma unroll
        for (int r = 0; r < R; r++) {
            ULL d2 = 0ull, df;
            df = add2(x2[r][0], p0.x); d2 = fma2(df, df, d2);
            df = add2(x2[r][1], p0.y); d2 = fma2(df, df, d2);
            df = add2(x2[r][2], p1.x); d2 = fma2(df, df, d2);
            df = add2(x2[r][3], p1.y); d2 = fma2(df, df, d2);
            df = add2(x2[r][4], p2.x); d2 = fma2(df, df, d2);
            df = add2(x2[r][5], p2.y); d2 = fma2(df, df, d2);
            df = add2(x2[r][6], p3.x); d2 = fma2(df, df, d2);
            df = add2(x2[r][7], p3.y); d2 = fma2(df, df, d2);
            df = add2(x2[r][8], p4.x); d2 = fma2(df, df, d2);
            df = add2(x2[r][9], p4.y); d2 = fma2(df, df, d2);
            float ss, ssh; upk2(d2, ss, ssh);
            ev[r] = __expf(-sqrtf(ss));
            den[r] += ev[r];
        }

        // ---- expert MLP, hidden units packed (h, h+1) per lane ----
        ULL pred2[R];
        #pragma unroll
        for (int r = 0; r < R; r++) pred2[r] = 0ull;

        #pragma unroll
        for (int hp = 0; hp < NHP; hp++) {
            const ulonglong2* wrow = (const ulonglong2*)(w1p + (k * NHP + hp) * DI);
            ulonglong2 w0 = wrow[0], w1v = wrow[1], w2v = wrow[2], w3 = wrow[3], w4 = wrow[4];
            ulonglong2 bwv = ((const ulonglong2*)bwp)[k * NHP + hp]; // (b1pair, w2pair)
            #pragma unroll
            for (int r = 0; r < R; r++) {
                ULL acc = bwv.x;
                acc = fma2(x2[r][0], w0.x,  acc);
                acc = fma2(x2[r][1], w0.y,  acc);
                acc = fma2(x2[r][2], w1v.x, acc);
                acc = fma2(x2[r][3], w1v.y, acc);
                acc = fma2(x2[r][4], w2v.x, acc);
                acc = fma2(x2[r][5], w2v.y, acc);
                acc = fma2(x2[r][6], w3.x,  acc);
                acc = fma2(x2[r][7], w3.y,  acc);
                acc = fma2(x2[r][8], w4.x,  acc);
                acc = fma2(x2[r][9], w4.y,  acc);
                float hl, hh; upk2(acc, hl, hh);
                hl = fmaxf(hl, 0.0f);
                hh = fmaxf(hh, 0.0f);
                pred2[r] = fma2(pk2(hl, hh), bwv.y, pred2[r]);
            }
        }

        float b2k = sm[F_B2 + k];
        #pragma unroll
        for (int r = 0; r < R; r++) {
            float pl, ph; upk2(pred2[r], pl, ph);
            float pred = b2k + pl + ph;
            num[r] = fmaf(pred, ev[r], num[r]);
        }
    }

    float4 o;
    o.x = num[0] / den[0];
    o.y = num[1] / den[1];
    o.z = num[2] / den[2];
    o.w = num[3] / den[3];
    ((float4*)out)[gt] = o;
}

extern "C" void kernel_launch(void* const* d_in, const int* in_sizes, int n_in,
                              void* d_out, int out_size)
{
    const float* in    = (const float*)d_in[0];
    const float* W1    = (const float*)d_in[1];
    const float* b1    = (const float*)d_in[2];
    const float* W2    = (const float*)d_in[3];
    const float* b2    = (const float*)d_in[4];
    const float* proto = (const float*)d_in[5];
    float* out = (float*)d_out;

    piecewise_mlp_kernel<<<GRID, THREADS, SM_FLOATS * sizeof(float)>>>(
        in, W1, b1, W2, b2, proto, out);
}